// round 5
// baseline (speedup 1.0000x reference)
#include <cuda_runtime.h>

#define B_    4
#define N_    2048
#define INF_  512
#define D_    64
#define H_    8
#define BH_   32
#define NCHUNK 32          // 64 ranks per chunk
#define CHSZ   64

// ---------------- scratch (device globals; no allocation) ----------------
__device__ __align__(16) float g_V[B_ * N_ * D_];            // (b, n, 64)
__device__ float g_Q[BH_ * N_];                              // (b*8+h, n)
__device__ float g_K[BH_ * N_];
__device__ int   g_si[BH_ * N_];                             // sorted index
__device__ float g_e1[BH_ * N_];                             // exp(Qsorted)
__device__ float g_e2[BH_ * N_];                             // exp(0.01*Qsorted)
__device__ float g_pe1[BH_ * (N_ + 1)];                      // exclusive scalar prefix of e1
__device__ float g_pe2[BH_ * (N_ + 1)];
__device__ int   g_t[BH_ * N_];                              // rank t_i per output row
__device__ float g_cstart[BH_ * NCHUNK * 128];               // chunk-start running sums, col=2f+pn
__device__ float g_tot[BH_ * 128];                           // column totals (interleaved P,N)
__device__ int   g_bcnt[BH_ * NCHUNK];                       // bucket counts
__device__ int   g_blist[BH_ * NCHUNK * N_];                 // bucket member lists

// ---------------- Kernel A: pipelined V = X@Wv + bv, then Q,K projections
// 512 threads, 64x64 tile, 2x4 micro-tile, double-buffered smem.
__global__ void __launch_bounds__(512) kernelA(
    const float* __restrict__ X,  const float* __restrict__ Wv, const float* __restrict__ bv,
    const float* __restrict__ Wq, const float* __restrict__ bq,
    const float* __restrict__ Wk, const float* __restrict__ bk)
{
    __shared__ __align__(16) float XsT[2][32][66];   // transposed: [buf][k][row], pad 66
    __shared__ __align__(16) float Ws[2][32][64];    // [buf][k][col]
    __shared__ __align__(16) float Vs[64][65];

    int tid = threadIdx.x;
    int tx = tid & 15, ty = tid >> 4;           // ty: 0..31 (2 rows each)
    int row0 = blockIdx.x * 64;                 // global row over b*N_

    // load assignments: 512 float4 per ktile for each of X, W -> 1 per thread
    int xr = tid >> 3, xk = tid & 7;            // X: row 0..63, k-group 0..7
    int wk = tid >> 4, wc = tid & 15;           // W: k 0..31, col-group 0..15

    const float* Xr = X + (size_t)(row0 + xr) * INF_ + xk * 4;

    float4 xa, wa;
    // prologue: load ktile 0
    xa = *(const float4*)(Xr);
    wa = *(const float4*)&Wv[wk * 64 + wc * 4];
    XsT[0][xk * 4 + 0][xr] = xa.x; XsT[0][xk * 4 + 1][xr] = xa.y;
    XsT[0][xk * 4 + 2][xr] = xa.z; XsT[0][xk * 4 + 3][xr] = xa.w;
    *(float4*)&Ws[0][wk][wc * 4] = wa;
    __syncthreads();

    float acc[2][4] = {};

#pragma unroll 1
    for (int kt = 0; kt < 16; ++kt) {
        int p = kt & 1;
        if (kt < 15) {
            int o = (kt + 1) * 32;
            xa = *(const float4*)(Xr + o);
            wa = *(const float4*)&Wv[(o + wk) * 64 + wc * 4];
        }
#pragma unroll
        for (int kk = 0; kk < 32; ++kk) {
            float2 av = *(const float2*)&XsT[p][kk][ty * 2];
            float4 bw = *(const float4*)&Ws[p][kk][tx * 4];
            acc[0][0] += av.x * bw.x; acc[0][1] += av.x * bw.y; acc[0][2] += av.x * bw.z; acc[0][3] += av.x * bw.w;
            acc[1][0] += av.y * bw.x; acc[1][1] += av.y * bw.y; acc[1][2] += av.y * bw.z; acc[1][3] += av.y * bw.w;
        }
        if (kt < 15) {
            int np = p ^ 1;
            XsT[np][xk * 4 + 0][xr] = xa.x; XsT[np][xk * 4 + 1][xr] = xa.y;
            XsT[np][xk * 4 + 2][xr] = xa.z; XsT[np][xk * 4 + 3][xr] = xa.w;
            *(float4*)&Ws[np][wk][wc * 4] = wa;
            __syncthreads();
        }
    }

    float b0 = bv[tx * 4 + 0], b1 = bv[tx * 4 + 1], b2 = bv[tx * 4 + 2], b3 = bv[tx * 4 + 3];
#pragma unroll
    for (int i = 0; i < 2; ++i) {
        Vs[ty * 2 + i][tx * 4 + 0] = acc[i][0] + b0;
        Vs[ty * 2 + i][tx * 4 + 1] = acc[i][1] + b1;
        Vs[ty * 2 + i][tx * 4 + 2] = acc[i][2] + b2;
        Vs[ty * 2 + i][tx * 4 + 3] = acc[i][3] + b3;
    }
    __syncthreads();

    // write V
#pragma unroll
    for (int i = 0; i < 2; ++i) {
        float4 v = make_float4(Vs[ty * 2 + i][tx * 4 + 0], Vs[ty * 2 + i][tx * 4 + 1],
                               Vs[ty * 2 + i][tx * 4 + 2], Vs[ty * 2 + i][tx * 4 + 3]);
        *(float4*)&g_V[(size_t)(row0 + ty * 2 + i) * 64 + tx * 4] = v;
    }

    // Q, K projections: 64 rows x 8 heads; 512 threads -> 1 (row, head) each
    int bb_ = row0 >> 11;               // batch
    int n0  = row0 & (N_ - 1);
    int r   = tid >> 3;
    int h   = tid & 7;
    float q = bq[h], k = bk[h];
#pragma unroll 8
    for (int f = 0; f < 64; ++f) {
        float v = Vs[r][f];
        q += v * Wq[f * 8 + h];
        k += v * Wk[f * 8 + h];
    }
    int n = n0 + r;
    g_Q[(bb_ * 8 + h) * N_ + n] = q;
    g_K[(bb_ * 8 + h) * N_ + n] = k;
}

// ------------- Kernel B1: STABLE 8-bit x 4-pass radix sort + scans --------
// dynamic smem layout (elements):
//   key[2048] idx[2048] key2[2048] idx2[2048] e1[2048] e2[2048]
//   partP[32*64] partN[32*64] cnt[17408(padded 256x64)] wsum[32]
//   c1[128] c2[128] bcnt[32]
#define CNT_PAD(g) ((g) + ((g) >> 4))
#define CNT_ELEMS  (16384 + 1024)
#define B1_SMEM_BYTES ((8 * 2048 + CNT_ELEMS + 32 + 128 + 128 + 32) * 4)

__device__ __forceinline__ unsigned f2u_order(float f) {
    unsigned u = __float_as_uint(f);
    return u ^ ((u >> 31) ? 0xFFFFFFFFu : 0x80000000u);
}

__global__ void __launch_bounds__(1024) kernelB1()
{
    extern __shared__ __align__(16) char smemRaw[];
    unsigned* key   = (unsigned*)smemRaw;
    int*      idx   = (int*)(key + 2048);
    unsigned* key2  = (unsigned*)(idx + 2048);
    int*      idx2  = (int*)(key2 + 2048);
    float*    e1    = (float*)(idx2 + 2048);
    float*    e2    = e1 + 2048;
    float*    partP = e2 + 2048;              // [32][64]
    float*    partN = partP + 2048;
    int*      cnt   = (int*)(partN + 2048);   // padded [256][64] digit-major
    int*      wsum  = cnt + CNT_ELEMS;        // 32
    float*    c1    = (float*)(wsum + 32);    // 128
    float*    c2    = c1 + 128;
    int*      bcnt  = (int*)(c2 + 128);       // 32

    int bh = blockIdx.x;
    int b  = bh >> 3;
    int tid = threadIdx.x;
    int lane = tid & 31;
    unsigned ltmask = (lane == 0) ? 0u : (0xFFFFFFFFu >> (32 - lane));

    // load + order-preserving transform
    for (int r = tid; r < N_; r += 1024) {
        key[r] = f2u_order(g_Q[bh * N_ + r]);
        idx[r] = r;
    }
    __syncthreads();

    // STABLE 8-bit LSD radix sort, 4 passes.
    // Logical warps: positions 0..1023 -> lw 0..31, 1024..2047 -> lw 32..63.
    unsigned* kin = key;  unsigned* kout = key2;
    int*      iin = idx;  int*      iout = idx2;
    int lw0 = tid >> 5, lw1 = 32 + (tid >> 5);
#pragma unroll
    for (int pass = 0; pass < 4; ++pass) {
        int shift = pass * 8;
        // zero the 16 counter slots this thread owns (padded layout)
#pragma unroll
        for (int j = 0; j < 16; ++j) cnt[CNT_PAD(tid * 16 + j)] = 0;
        __syncthreads();

        unsigned k0 = kin[tid], k1 = kin[tid + 1024];
        int      i0 = iin[tid], i1 = iin[tid + 1024];
        int d0 = (k0 >> shift) & 255, d1 = (k1 >> shift) & 255;

        unsigned m0 = __match_any_sync(0xFFFFFFFFu, d0);
        unsigned m1 = __match_any_sync(0xFFFFFFFFu, d1);
        int r0 = __popc(m0 & ltmask);
        int r1 = __popc(m1 & ltmask);
        if (r0 == 0) cnt[CNT_PAD(d0 * 64 + lw0)] = __popc(m0);
        if (r1 == 0) cnt[CNT_PAD(d1 * 64 + lw1)] = __popc(m1);
        __syncthreads();

        // block exclusive scan of 16384 counters (16 serial per thread)
        int v[16]; int s = 0;
#pragma unroll
        for (int j = 0; j < 16; ++j) { v[j] = cnt[CNT_PAD(tid * 16 + j)]; s += v[j]; }
        int inc = s;
#pragma unroll
        for (int off = 1; off < 32; off <<= 1) {
            int nn = __shfl_up_sync(0xFFFFFFFFu, inc, off);
            if (lane >= off) inc += nn;
        }
        if (lane == 31) wsum[tid >> 5] = inc;
        __syncthreads();
        if (tid < 32) {
            int wv = wsum[tid];
            int winc = wv;
#pragma unroll
            for (int off = 1; off < 32; off <<= 1) {
                int nn = __shfl_up_sync(0xFFFFFFFFu, winc, off);
                if (tid >= off) winc += nn;
            }
            wsum[tid] = winc - wv;   // exclusive
        }
        __syncthreads();
        int run = inc - s + wsum[tid >> 5];
#pragma unroll
        for (int j = 0; j < 16; ++j) { cnt[CNT_PAD(tid * 16 + j)] = run; run += v[j]; }
        __syncthreads();

        int p0 = cnt[CNT_PAD(d0 * 64 + lw0)] + r0;
        int p1 = cnt[CNT_PAD(d1 * 64 + lw1)] + r1;
        kout[p0] = k0; iout[p0] = i0;
        kout[p1] = k1; iout[p1] = i1;
        __syncthreads();
        unsigned* tk = kin; kin = kout; kout = tk;
        int*      ti = iin; iin = iout; iout = ti;
    }
    // after 4 passes sorted data is back in key / idx

    // exp tables + publish sorted order
    for (int r = tid; r < N_; r += 1024) {
        unsigned u = key[r];
        float q = __uint_as_float(u ^ ((u >> 31) ? 0x80000000u : 0xFFFFFFFFu));
        float x1 = __expf(q), x2 = __expf(0.01f * q);
        e1[r] = x1; e2[r] = x2;
        g_si[bh * N_ + r] = idx[r];
        g_e1[bh * N_ + r] = x1;
        g_e2[bh * N_ + r] = x2;
    }
    if (tid < NCHUNK) bcnt[tid] = 0;
    __syncthreads();

    // ranks (binary search in uint key domain) + chunk buckets
    for (int i = tid; i < N_; i += 1024) {
        unsigned tu = f2u_order(-g_K[bh * N_ + i]);
        int lo = 0, hi = N_;
        while (lo < hi) {
            int mid = (lo + hi) >> 1;
            if (key[mid] <= tu) lo = mid + 1; else hi = mid;
        }
        g_t[bh * N_ + i] = lo;
        int c = lo >> 6; if (c > NCHUNK - 1) c = NCHUNK - 1;   // t==2048 -> chunk 31
        int pos = atomicAdd(&bcnt[c], 1);
        g_blist[(bh * NCHUNK + c) * N_ + pos] = i;
    }

    // chunk partial vector sums
    {
        int f = tid & 63, g = tid >> 6;          // g: 0..15
        int r0 = g * 128;
        float aP = 0.f, aN = 0.f;
        for (int r = r0; r < r0 + 64; ++r) {
            float v = g_V[((size_t)b * N_ + idx[r]) * 64 + f];
            aP += e1[r] * v; aN += e2[r] * v;
        }
        partP[(2 * g) * 64 + f] = aP; partN[(2 * g) * 64 + f] = aN;
        float bP = 0.f, bN = 0.f;
        for (int r = r0 + 64; r < r0 + 128; ++r) {
            float v = g_V[((size_t)b * N_ + idx[r]) * 64 + f];
            bP += e1[r] * v; bN += e2[r] * v;
        }
        partP[(2 * g + 1) * 64 + f] = bP; partN[(2 * g + 1) * 64 + f] = bN;
    }
    __syncthreads();

    // exclusive scan over chunks -> g_cstart, totals -> g_tot
    if (tid < 64) {
        float run = 0.f;
        for (int gg = 0; gg < NCHUNK; ++gg) {
            float t = partP[gg * 64 + tid];
            g_cstart[(bh * NCHUNK + gg) * 128 + 2 * tid] = run;
            run += t;
        }
        g_tot[bh * 128 + 2 * tid] = run;
    } else if (tid < 128) {
        int ff = tid - 64;
        float run = 0.f;
        for (int gg = 0; gg < NCHUNK; ++gg) {
            float t = partN[gg * 64 + ff];
            g_cstart[(bh * NCHUNK + gg) * 128 + 2 * ff + 1] = run;
            run += t;
        }
        g_tot[bh * 128 + 2 * ff + 1] = run;
    }

    // scalar exclusive scans of e1, e2
    if (tid < 128) {
        float s1 = 0.f, s2 = 0.f;
        for (int q = 0; q < 16; ++q) { s1 += e1[tid * 16 + q]; s2 += e2[tid * 16 + q]; }
        c1[tid] = s1; c2[tid] = s2;
    }
    __syncthreads();
    if (tid == 0) {
        float r1 = 0.f, r2 = 0.f;
        for (int q = 0; q < 128; ++q) {
            float t1 = c1[q], t2 = c2[q];
            c1[q] = r1; c2[q] = r2;
            r1 += t1; r2 += t2;
        }
        g_pe1[bh * (N_ + 1) + N_] = r1;
        g_pe2[bh * (N_ + 1) + N_] = r2;
    }
    __syncthreads();
    if (tid < 128) {
        float r1 = c1[tid], r2 = c2[tid];
        for (int q = 0; q < 16; ++q) {
            int r = tid * 16 + q;
            g_pe1[bh * (N_ + 1) + r] = r1;
            g_pe2[bh * (N_ + 1) + r] = r2;
            r1 += e1[r]; r2 += e2[r];
        }
    }
    if (tid < NCHUNK) g_bcnt[bh * NCHUNK + tid] = bcnt[tid];
}

// ------------- Kernel BC: per-chunk smem prefix + direct output ----------
__global__ void __launch_bounds__(256) kernelBC(float* __restrict__ out)
{
    __shared__ __align__(16) float contrib[CHSZ * 128];  // 64 ranks x 128 cols (P,N interleaved)
    __shared__ __align__(16) float colEnd[128];
    __shared__ __align__(16) float sTot[128];
    __shared__ float e1s[CHSZ], e2s[CHSZ];
    __shared__ int   sidx[CHSZ];
    __shared__ float sE1tot;

    int blk = blockIdx.x;
    int bh  = blk >> 5;          // 0..31
    int g   = blk & 31;          // chunk
    int b   = bh >> 3, h = bh & 7;
    int tid = threadIdx.x;
    int r0  = g * CHSZ;

    if (tid < CHSZ) {
        e1s[tid]  = g_e1[bh * N_ + r0 + tid];
        e2s[tid]  = g_e2[bh * N_ + r0 + tid];
        sidx[tid] = g_si[bh * N_ + r0 + tid];
    }
    if (tid >= 128 && tid < 256) sTot[tid - 128] = g_tot[bh * 128 + tid - 128];
    if (tid == 64) sE1tot = g_pe1[bh * (N_ + 1) + N_];
    __syncthreads();

    // gather weighted V rows: 64 rows x 64 f
    for (int id = tid; id < CHSZ * 64; id += 256) {
        int r = id >> 6, f = id & 63;
        float v = g_V[((size_t)b * N_ + sidx[r]) * 64 + f];
        *(float2*)&contrib[r * 128 + 2 * f] = make_float2(e1s[r] * v, e2s[r] * v);
    }
    __syncthreads();

    // in-place exclusive scan along ranks, one column per thread (128 cols)
    if (tid < 128) {
        float run = g_cstart[(bh * NCHUNK + g) * 128 + tid];
#pragma unroll 8
        for (int r = 0; r < CHSZ; ++r) {
            float t = contrib[r * 128 + tid];
            contrib[r * 128 + tid] = run;
            run += t;
        }
        colEnd[tid] = run;
    }
    __syncthreads();

    // outputs: one warp per row i
    int cnt  = g_bcnt[bh * NCHUNK + g];
    int w    = tid >> 5, lane = tid & 31;
    float e1tot = sE1tot;
    for (int ii = w; ii < cnt; ii += 8) {
        int   i  = g_blist[(bh * NCHUNK + g) * N_ + ii];
        int   t  = g_t[bh * N_ + i];
        int   local = t - r0;
        float kv = g_K[bh * N_ + i];
        float ek  = __expf(kv);
        float ek2 = __expf(0.01f * kv);
        float pe1 = g_pe1[bh * (N_ + 1) + t];
        float pe2 = g_pe2[bh * (N_ + 1) + t];
        float denom = ek * (e1tot - pe1) + ek2 * pe2;
        float inv = 1.0f / denom;

        const float* row = (local < CHSZ) ? &contrib[local * 128] : colEnd;
        float4 c = *(const float4*)&row[lane * 4];
        float o0 = (ek * (sTot[lane * 4 + 0] - c.x) + ek2 * c.y) * inv;
        float o1 = (ek * (sTot[lane * 4 + 2] - c.z) + ek2 * c.w) * inv;
        *(float2*)&out[((size_t)(b * N_ + i)) * 512 + h * 64 + lane * 2] = make_float2(o0, o1);
    }
}

// ------------- launch -----------------------------------------------------
extern "C" void kernel_launch(void* const* d_in, const int* in_sizes, int n_in,
                              void* d_out, int out_size)
{
    const float* X  = (const float*)d_in[0];
    const float* Wv = (const float*)d_in[1];
    const float* bv = (const float*)d_in[2];
    const float* Wq = (const float*)d_in[3];
    const float* bq = (const float*)d_in[4];
    const float* Wk = (const float*)d_in[5];
    const float* bk = (const float*)d_in[6];

    cudaFuncSetAttribute(kernelB1, cudaFuncAttributeMaxDynamicSharedMemorySize, B1_SMEM_BYTES);

    kernelA<<<(B_ * N_) / 64, 512>>>(X, Wv, bv, Wq, bq, Wk, bk);
    kernelB1<<<BH_, 1024, B1_SMEM_BYTES>>>();
    kernelBC<<<BH_ * NCHUNK, 256>>>((float*)d_out);
}

// round 6
// speedup vs baseline: 1.0436x; 1.0436x over previous
#include <cuda_runtime.h>

#define B_    4
#define N_    2048
#define INF_  512
#define D_    64
#define H_    8
#define BH_   32
#define NCHUNK 32          // 64 ranks per chunk
#define CHSZ   64

// ---------------- scratch (device globals; no allocation) ----------------
__device__ __align__(16) float g_V[B_ * N_ * D_];            // (b, n, 64)
__device__ float g_Q[BH_ * N_];                              // (b*8+h, n)
__device__ float g_K[BH_ * N_];
__device__ int   g_si[BH_ * N_];                             // sorted index
__device__ float g_e1[BH_ * N_];                             // exp(Qsorted)
__device__ float g_e2[BH_ * N_];                             // exp(0.01*Qsorted)
__device__ float g_pe1[BH_ * (N_ + 1)];                      // exclusive scalar prefix of e1
__device__ float g_pe2[BH_ * (N_ + 1)];
__device__ int   g_t[BH_ * N_];                              // rank t_i per output row
__device__ float g_cstart[BH_ * NCHUNK * 128];               // chunk-start running sums, col=2f+pn
__device__ float g_tot[BH_ * 128];                           // column totals (interleaved P,N)
__device__ int   g_bcnt[BH_ * NCHUNK];                       // bucket counts
__device__ int   g_blist[BH_ * NCHUNK * N_];                 // bucket member lists

// ---------------- tf32 helpers -------------------------------------------
__device__ __forceinline__ unsigned f2tf32(float x) {
    unsigned r;
    asm("cvt.rna.tf32.f32 %0, %1;" : "=r"(r) : "f"(x));
    return r;
}
__device__ __forceinline__ void mma_tf32(float c[4],
    unsigned a0, unsigned a1, unsigned a2, unsigned a3,
    unsigned b0, unsigned b1)
{
    asm volatile(
        "mma.sync.aligned.m16n8k8.row.col.f32.tf32.tf32.f32 "
        "{%0,%1,%2,%3}, {%4,%5,%6,%7}, {%8,%9}, {%0,%1,%2,%3};"
        : "+f"(c[0]), "+f"(c[1]), "+f"(c[2]), "+f"(c[3])
        : "r"(a0), "r"(a1), "r"(a2), "r"(a3), "r"(b0), "r"(b1));
}

// ---------------- Kernel A: tf32 tensor-core V = X@Wv + bv, then Q,K -----
// 128 CTAs x 256 thr. CTA: 64 rows x 64 cols, K=512 in 16 tiles of 32.
// dynamic smem (floats): Xs[2][64][36]=4608, Ws[2][32][72]=4608, Vs[64][65]=4160
#define SMEMA_BYTES ((4608 + 4608 + 4160) * 4)

__global__ void __launch_bounds__(256) kernelA(
    const float* __restrict__ X,  const float* __restrict__ Wv, const float* __restrict__ bv,
    const float* __restrict__ Wq, const float* __restrict__ bq,
    const float* __restrict__ Wk, const float* __restrict__ bk)
{
    extern __shared__ __align__(16) float sm[];
    float* Xs  = sm;            // [2][64][36]
    float* Wsm = sm + 4608;     // [2][32][72]
    float* Vs  = sm + 9216;     // [64][65]

    int tid  = threadIdx.x;
    int lane = tid & 31, w = tid >> 5;
    int g = lane >> 2, t = lane & 3;
    int row0 = blockIdx.x * 64;                 // global row over b*N_

    // global load assignments: 2 float4 each for X and W per ktile
    int xr = tid >> 2, xk = (tid & 3) * 8;      // X: row 0..63, 8 floats
    int wk = tid >> 3, wc = (tid & 7) * 8;      // W: k 0..31, 8 floats
    const float* Xp = X + (size_t)(row0 + xr) * INF_ + xk;

    float4 xv0, xv1, wv0, wv1;
    // prologue: ktile 0
    xv0 = *(const float4*)(Xp);
    xv1 = *(const float4*)(Xp + 4);
    wv0 = *(const float4*)&Wv[wk * 64 + wc];
    wv1 = *(const float4*)&Wv[wk * 64 + wc + 4];
    *(float4*)&Xs[xr * 36 + xk]     = xv0;
    *(float4*)&Xs[xr * 36 + xk + 4] = xv1;
    *(float4*)&Wsm[wk * 72 + wc]     = wv0;
    *(float4*)&Wsm[wk * 72 + wc + 4] = wv1;
    __syncthreads();

    int rw  = (w >> 1) * 16;        // warp row base
    int nc0 = (w & 1) * 32;         // warp col base
    float acc[4][4] = {};

#pragma unroll 1
    for (int kt = 0; kt < 16; ++kt) {
        int p = kt & 1, pb = p * 2304;
        if (kt < 15) {
            int o = (kt + 1) * 32;
            xv0 = *(const float4*)(Xp + o);
            xv1 = *(const float4*)(Xp + o + 4);
            wv0 = *(const float4*)&Wv[(o + wk) * 64 + wc];
            wv1 = *(const float4*)&Wv[(o + wk) * 64 + wc + 4];
        }
#pragma unroll
        for (int ks = 0; ks < 32; ks += 8) {
            float af0 = Xs[pb + (rw + g)     * 36 + ks + t];
            float af1 = Xs[pb + (rw + g + 8) * 36 + ks + t];
            float af2 = Xs[pb + (rw + g)     * 36 + ks + t + 4];
            float af3 = Xs[pb + (rw + g + 8) * 36 + ks + t + 4];
            unsigned ah0 = f2tf32(af0), ah1 = f2tf32(af1), ah2 = f2tf32(af2), ah3 = f2tf32(af3);
            unsigned al0 = f2tf32(af0 - __uint_as_float(ah0));
            unsigned al1 = f2tf32(af1 - __uint_as_float(ah1));
            unsigned al2 = f2tf32(af2 - __uint_as_float(ah2));
            unsigned al3 = f2tf32(af3 - __uint_as_float(ah3));
#pragma unroll
            for (int nt = 0; nt < 4; ++nt) {
                float bf0 = Wsm[pb + (ks + t)     * 72 + nc0 + nt * 8 + g];
                float bf1 = Wsm[pb + (ks + t + 4) * 72 + nc0 + nt * 8 + g];
                unsigned bh0 = f2tf32(bf0), bh1 = f2tf32(bf1);
                unsigned bl0 = f2tf32(bf0 - __uint_as_float(bh0));
                unsigned bl1 = f2tf32(bf1 - __uint_as_float(bh1));
                mma_tf32(acc[nt], ah0, ah1, ah2, ah3, bh0, bh1);
                mma_tf32(acc[nt], ah0, ah1, ah2, ah3, bl0, bl1);
                mma_tf32(acc[nt], al0, al1, al2, al3, bh0, bh1);
            }
        }
        if (kt < 15) {
            int np = (kt + 1) & 1, nb = np * 2304;
            *(float4*)&Xs[nb * 1 + xr * 36 + xk]     = xv0;   // nb already scaled? no: see below
            *(float4*)&Xs[nb + xr * 36 + xk + 4] = xv1;
            *(float4*)&Wsm[nb + wk * 72 + wc]     = wv0;
            *(float4*)&Wsm[nb + wk * 72 + wc + 4] = wv1;
            __syncthreads();
        }
    }

    // epilogue: acc -> Vs (+bias)
#pragma unroll
    for (int nt = 0; nt < 4; ++nt) {
        int col = nc0 + nt * 8 + 2 * t;
        float bvl0 = bv[col], bvl1 = bv[col + 1];
        Vs[(rw + g)     * 65 + col]     = acc[nt][0] + bvl0;
        Vs[(rw + g)     * 65 + col + 1] = acc[nt][1] + bvl1;
        Vs[(rw + g + 8) * 65 + col]     = acc[nt][2] + bvl0;
        Vs[(rw + g + 8) * 65 + col + 1] = acc[nt][3] + bvl1;
    }
    __syncthreads();

    // write V
    for (int id = tid; id < 64 * 16; id += 256) {
        int r = id >> 4, fq = (id & 15) * 4;
        float4 v = make_float4(Vs[r * 65 + fq], Vs[r * 65 + fq + 1],
                               Vs[r * 65 + fq + 2], Vs[r * 65 + fq + 3]);
        *(float4*)&g_V[(size_t)(row0 + r) * 64 + fq] = v;
    }

    // Q, K projections: 64 rows x 8 heads; each thread does 2 heads of 1 row
    int bb_ = row0 >> 11;               // batch
    int n0  = row0 & (N_ - 1);
    int r   = tid >> 2;
    int hp  = (tid & 3) * 2;
    float q0 = bq[hp], q1 = bq[hp + 1];
    float k0 = bk[hp], k1 = bk[hp + 1];
#pragma unroll 8
    for (int f = 0; f < 64; ++f) {
        float v = Vs[r * 65 + f];
        q0 += v * Wq[f * 8 + hp]; q1 += v * Wq[f * 8 + hp + 1];
        k0 += v * Wk[f * 8 + hp]; k1 += v * Wk[f * 8 + hp + 1];
    }
    int n = n0 + r;
    g_Q[(bb_ * 8 + hp) * N_ + n]     = q0;
    g_Q[(bb_ * 8 + hp + 1) * N_ + n] = q1;
    g_K[(bb_ * 8 + hp) * N_ + n]     = k0;
    g_K[(bb_ * 8 + hp + 1) * N_ + n] = k1;
}

// ------------- Kernel B1: STABLE 4-bit x 8-pass radix sort + scans --------
#define B1_SMEM_BYTES ((8 * 2048 + 1024 + 32 + 128 + 128 + 32) * 4)

__device__ __forceinline__ unsigned f2u_order(float f) {
    unsigned u = __float_as_uint(f);
    return u ^ ((u >> 31) ? 0xFFFFFFFFu : 0x80000000u);
}

__global__ void __launch_bounds__(1024) kernelB1()
{
    extern __shared__ __align__(16) char smemRaw[];
    unsigned* key   = (unsigned*)smemRaw;
    int*      idx   = (int*)(key + 2048);
    unsigned* key2  = (unsigned*)(idx + 2048);
    int*      idx2  = (int*)(key2 + 2048);
    float*    e1    = (float*)(idx2 + 2048);
    float*    e2    = e1 + 2048;
    float*    partP = e2 + 2048;              // [32][64]
    float*    partN = partP + 2048;
    int*      cnt   = (int*)(partN + 2048);   // [16][64] digit-major
    int*      wsum  = cnt + 1024;             // 32
    float*    c1    = (float*)(wsum + 32);    // 128
    float*    c2    = c1 + 128;
    int*      bcnt  = (int*)(c2 + 128);       // 32

    int bh = blockIdx.x;
    int b  = bh >> 3;
    int tid = threadIdx.x;
    int lane = tid & 31;
    unsigned ltmask = (lane == 0) ? 0u : (0xFFFFFFFFu >> (32 - lane));

    for (int r = tid; r < N_; r += 1024) {
        key[r] = f2u_order(g_Q[bh * N_ + r]);
        idx[r] = r;
    }
    __syncthreads();

    unsigned* kin = key;  unsigned* kout = key2;
    int*      iin = idx;  int*      iout = idx2;
    int lw0 = tid >> 5, lw1 = 32 + (tid >> 5);
#pragma unroll
    for (int pass = 0; pass < 8; ++pass) {
        int shift = pass * 4;
        cnt[tid] = 0;
        __syncthreads();

        unsigned k0 = kin[tid], k1 = kin[tid + 1024];
        int      i0 = iin[tid], i1 = iin[tid + 1024];
        int d0 = (k0 >> shift) & 15, d1 = (k1 >> shift) & 15;

        unsigned m0 = __match_any_sync(0xFFFFFFFFu, d0);
        unsigned m1 = __match_any_sync(0xFFFFFFFFu, d1);
        int r0 = __popc(m0 & ltmask);
        int r1 = __popc(m1 & ltmask);
        if (r0 == 0) cnt[d0 * 64 + lw0] = __popc(m0);
        if (r1 == 0) cnt[d1 * 64 + lw1] = __popc(m1);
        __syncthreads();

        int v = cnt[tid];
        int inc = v;
#pragma unroll
        for (int off = 1; off < 32; off <<= 1) {
            int nn = __shfl_up_sync(0xFFFFFFFFu, inc, off);
            if (lane >= off) inc += nn;
        }
        if (lane == 31) wsum[tid >> 5] = inc;
        __syncthreads();
        if (tid < 32) {
            int wv = wsum[tid];
            int winc = wv;
#pragma unroll
            for (int off = 1; off < 32; off <<= 1) {
                int nn = __shfl_up_sync(0xFFFFFFFFu, winc, off);
                if (tid >= off) winc += nn;
            }
            wsum[tid] = winc - wv;   // exclusive
        }
        __syncthreads();
        cnt[tid] = inc - v + wsum[tid >> 5];   // exclusive global offset
        __syncthreads();

        int p0 = cnt[d0 * 64 + lw0] + r0;
        int p1 = cnt[d1 * 64 + lw1] + r1;
        kout[p0] = k0; iout[p0] = i0;
        kout[p1] = k1; iout[p1] = i1;
        __syncthreads();
        unsigned* tk = kin; kin = kout; kout = tk;
        int*      ti = iin; iin = iout; iout = ti;
    }

    for (int r = tid; r < N_; r += 1024) {
        unsigned u = key[r];
        float q = __uint_as_float(u ^ ((u >> 31) ? 0x80000000u : 0xFFFFFFFFu));
        float x1 = __expf(q), x2 = __expf(0.01f * q);
        e1[r] = x1; e2[r] = x2;
        g_si[bh * N_ + r] = idx[r];
        g_e1[bh * N_ + r] = x1;
        g_e2[bh * N_ + r] = x2;
    }
    if (tid < NCHUNK) bcnt[tid] = 0;
    __syncthreads();

    for (int i = tid; i < N_; i += 1024) {
        unsigned tu = f2u_order(-g_K[bh * N_ + i]);
        int lo = 0, hi = N_;
        while (lo < hi) {
            int mid = (lo + hi) >> 1;
            if (key[mid] <= tu) lo = mid + 1; else hi = mid;
        }
        g_t[bh * N_ + i] = lo;
        int c = lo >> 6; if (c > NCHUNK - 1) c = NCHUNK - 1;   // t==2048 -> chunk 31
        int pos = atomicAdd(&bcnt[c], 1);
        g_blist[(bh * NCHUNK + c) * N_ + pos] = i;
    }

    {
        int f = tid & 63, g = tid >> 6;          // g: 0..15
        int r0 = g * 128;
        float aP = 0.f, aN = 0.f;
        for (int r = r0; r < r0 + 64; ++r) {
            float v = g_V[((size_t)b * N_ + idx[r]) * 64 + f];
            aP += e1[r] * v; aN += e2[r] * v;
        }
        partP[(2 * g) * 64 + f] = aP; partN[(2 * g) * 64 + f] = aN;
        float bP = 0.f, bN = 0.f;
        for (int r = r0 + 64; r < r0 + 128; ++r) {
            float v = g_V[((size_t)b * N_ + idx[r]) * 64 + f];
            bP += e1[r] * v; bN += e2[r] * v;
        }
        partP[(2 * g + 1) * 64 + f] = bP; partN[(2 * g + 1) * 64 + f] = bN;
    }
    __syncthreads();

    if (tid < 64) {
        float run = 0.f;
        for (int gg = 0; gg < NCHUNK; ++gg) {
            float t = partP[gg * 64 + tid];
            g_cstart[(bh * NCHUNK + gg) * 128 + 2 * tid] = run;
            run += t;
        }
        g_tot[bh * 128 + 2 * tid] = run;
    } else if (tid < 128) {
        int ff = tid - 64;
        float run = 0.f;
        for (int gg = 0; gg < NCHUNK; ++gg) {
            float t = partN[gg * 64 + ff];
            g_cstart[(bh * NCHUNK + gg) * 128 + 2 * ff + 1] = run;
            run += t;
        }
        g_tot[bh * 128 + 2 * ff + 1] = run;
    }

    if (tid < 128) {
        float s1 = 0.f, s2 = 0.f;
        for (int q = 0; q < 16; ++q) { s1 += e1[tid * 16 + q]; s2 += e2[tid * 16 + q]; }
        c1[tid] = s1; c2[tid] = s2;
    }
    __syncthreads();
    if (tid == 0) {
        float r1 = 0.f, r2 = 0.f;
        for (int q = 0; q < 128; ++q) {
            float t1 = c1[q], t2 = c2[q];
            c1[q] = r1; c2[q] = r2;
            r1 += t1; r2 += t2;
        }
        g_pe1[bh * (N_ + 1) + N_] = r1;
        g_pe2[bh * (N_ + 1) + N_] = r2;
    }
    __syncthreads();
    if (tid < 128) {
        float r1 = c1[tid], r2 = c2[tid];
        for (int q = 0; q < 16; ++q) {
            int r = tid * 16 + q;
            g_pe1[bh * (N_ + 1) + r] = r1;
            g_pe2[bh * (N_ + 1) + r] = r2;
            r1 += e1[r]; r2 += e2[r];
        }
    }
    if (tid < NCHUNK) g_bcnt[bh * NCHUNK + tid] = bcnt[tid];
}

// ------------- Kernel BC: per-chunk smem prefix + direct output ----------
__global__ void __launch_bounds__(256) kernelBC(float* __restrict__ out)
{
    __shared__ __align__(16) float contrib[CHSZ * 128];  // 64 ranks x 128 cols (P,N interleaved)
    __shared__ __align__(16) float colEnd[128];
    __shared__ __align__(16) float sTot[128];
    __shared__ float e1s[CHSZ], e2s[CHSZ];
    __shared__ int   sidx[CHSZ];
    __shared__ float sE1tot;

    int blk = blockIdx.x;
    int bh  = blk >> 5;          // 0..31
    int g   = blk & 31;          // chunk
    int b   = bh >> 3, h = bh & 7;
    int tid = threadIdx.x;
    int r0  = g * CHSZ;

    if (tid < CHSZ) {
        e1s[tid]  = g_e1[bh * N_ + r0 + tid];
        e2s[tid]  = g_e2[bh * N_ + r0 + tid];
        sidx[tid] = g_si[bh * N_ + r0 + tid];
    }
    if (tid >= 128 && tid < 256) sTot[tid - 128] = g_tot[bh * 128 + tid - 128];
    if (tid == 64) sE1tot = g_pe1[bh * (N_ + 1) + N_];
    __syncthreads();

    for (int id = tid; id < CHSZ * 64; id += 256) {
        int r = id >> 6, f = id & 63;
        float v = g_V[((size_t)b * N_ + sidx[r]) * 64 + f];
        *(float2*)&contrib[r * 128 + 2 * f] = make_float2(e1s[r] * v, e2s[r] * v);
    }
    __syncthreads();

    if (tid < 128) {
        float run = g_cstart[(bh * NCHUNK + g) * 128 + tid];
#pragma unroll 8
        for (int r = 0; r < CHSZ; ++r) {
            float t = contrib[r * 128 + tid];
            contrib[r * 128 + tid] = run;
            run += t;
        }
        colEnd[tid] = run;
    }
    __syncthreads();

    int cnt  = g_bcnt[bh * NCHUNK + g];
    int w    = tid >> 5, lane = tid & 31;
    float e1tot = sE1tot;
    for (int ii = w; ii < cnt; ii += 8) {
        int   i  = g_blist[(bh * NCHUNK + g) * N_ + ii];
        int   t  = g_t[bh * N_ + i];
        int   local = t - r0;
        float kv = g_K[bh * N_ + i];
        float ek  = __expf(kv);
        float ek2 = __expf(0.01f * kv);
        float pe1 = g_pe1[bh * (N_ + 1) + t];
        float pe2 = g_pe2[bh * (N_ + 1) + t];
        float denom = ek * (e1tot - pe1) + ek2 * pe2;
        float inv = 1.0f / denom;

        const float* row = (local < CHSZ) ? &contrib[local * 128] : colEnd;
        float4 c = *(const float4*)&row[lane * 4];
        float o0 = (ek * (sTot[lane * 4 + 0] - c.x) + ek2 * c.y) * inv;
        float o1 = (ek * (sTot[lane * 4 + 2] - c.z) + ek2 * c.w) * inv;
        *(float2*)&out[((size_t)(b * N_ + i)) * 512 + h * 64 + lane * 2] = make_float2(o0, o1);
    }
}

// ------------- launch -----------------------------------------------------
extern "C" void kernel_launch(void* const* d_in, const int* in_sizes, int n_in,
                              void* d_out, int out_size)
{
    const float* X  = (const float*)d_in[0];
    const float* Wv = (const float*)d_in[1];
    const float* bv = (const float*)d_in[2];
    const float* Wq = (const float*)d_in[3];
    const float* bq = (const float*)d_in[4];
    const float* Wk = (const float*)d_in[5];
    const float* bk = (const float*)d_in[6];

    cudaFuncSetAttribute(kernelA,  cudaFuncAttributeMaxDynamicSharedMemorySize, SMEMA_BYTES);
    cudaFuncSetAttribute(kernelB1, cudaFuncAttributeMaxDynamicSharedMemorySize, B1_SMEM_BYTES);

    kernelA<<<(B_ * N_) / 64, 256, SMEMA_BYTES>>>(X, Wv, bv, Wq, bq, Wk, bk);
    kernelB1<<<BH_, 1024, B1_SMEM_BYTES>>>();
    kernelBC<<<BH_ * NCHUNK, 256>>>((float*)d_out);
}